// round 6
// baseline (speedup 1.0000x reference)
#include <cuda_runtime.h>
#include <cstdint>

#define B_ 8
#define N_ 16384
#define M_ 1024
#define C_ 64
#define NS_ 32
#define COUT_ 67
#define R2_ 0.04f

// Scratch: transposed features (B, N, C) = 32 MB, and ball-query indices = 1 MB.
__device__ float g_ft[(size_t)B_ * N_ * C_];
__device__ int   g_idx[(size_t)B_ * M_ * NS_];

// ---------------------------------------------------------------------------
// Kernel 1: transpose features (B, C, N) -> (B, N, C), float4 both directions.
// ---------------------------------------------------------------------------
__global__ void transpose_kernel(const float* __restrict__ f) {
    __shared__ float tile[32][33];       // tile[c][n]
    const int b  = blockIdx.z;
    const int n0 = blockIdx.x * 32;
    const int c0 = blockIdx.y * 32;
    const int tx = threadIdx.x;          // 0..7
    const int ty = threadIdx.y;          // 0..31

    const float* src = f + (size_t)b * C_ * N_;
    float*       dst = g_ft + (size_t)b * N_ * C_;

    const float4 v = *(const float4*)(src + (size_t)(c0 + ty) * N_ + n0 + tx * 4);
    tile[ty][tx * 4 + 0] = v.x;
    tile[ty][tx * 4 + 1] = v.y;
    tile[ty][tx * 4 + 2] = v.z;
    tile[ty][tx * 4 + 3] = v.w;
    __syncthreads();

    float4 o;
    o.x = tile[tx * 4 + 0][ty];
    o.y = tile[tx * 4 + 1][ty];
    o.z = tile[tx * 4 + 2][ty];
    o.w = tile[tx * 4 + 3][ty];
    *(float4*)(dst + (size_t)(n0 + ty) * C_ + c0 + tx * 4) = o;
}

// ---------------------------------------------------------------------------
// Kernel 2: ball query — one warp per query, fully independent (no block
// coupling, no __syncthreads, no smem point tiles). Each iteration evaluates
// 128 points: all 12 coalesced loads issued up front (independent -> MLP=12,
// served from L1/L2 since every warp scans the same 192KB batch from index 0),
// then 4 ballots + guarded ordered placement. Warp exits the moment ITS query
// has 32 hits, so stragglers cost one warp slot, not a block.
// ---------------------------------------------------------------------------
__global__ void ballquery_kernel(const float* __restrict__ xyz,
                                 const float* __restrict__ new_xyz) {
    __shared__ int sidx[8][NS_];

    const int w    = threadIdx.x >> 5;
    const int lane = threadIdx.x & 31;
    const int q    = blockIdx.x * 8 + w;   // global query id
    const int b    = q >> 10;

    const float* xb = xyz + (size_t)b * N_ * 3;
    const float* qp = new_xyz + (size_t)q * 3;
    const float qx = qp[0], qy = qp[1], qz = qp[2];

    const unsigned ltm = (1u << lane) - 1u;
    int total = 0;

    for (int n0 = 0; n0 < N_; n0 += 128) {
        // Issue all loads for 4 groups of 32 points up front (independent).
        float px[4], py[4], pz[4];
#pragma unroll
        for (int g = 0; g < 4; g++) {
            const float* p = xb + (size_t)(n0 + g * 32 + lane) * 3;
            px[g] = p[0]; py[g] = p[1]; pz[g] = p[2];
        }

        unsigned msk[4];
#pragma unroll
        for (int g = 0; g < 4; g++) {
            const float dx = px[g] - qx;
            const float dy = py[g] - qy;
            const float dz = pz[g] - qz;
            msk[g] = __ballot_sync(0xffffffffu,
                                   dx * dx + dy * dy + dz * dz < R2_);
        }

#pragma unroll
        for (int g = 0; g < 4; g++) {
            if (msk[g]) {
                const int pos = total + __popc(msk[g] & ltm);
                if (((msk[g] >> lane) & 1u) && pos < NS_)
                    sidx[w][pos] = n0 + g * 32 + lane;
                total += __popc(msk[g]);
            }
        }
        if (total >= NS_) break;
    }

    __syncwarp();
    int v;
    if (total == 0) {
        v = N_ - 1;  // reference: all-invalid -> clamped gather
    } else {
        const int first = sidx[w][0];
        v = (lane < min(total, NS_)) ? sidx[w][lane] : first;
    }
    g_idx[(size_t)q * NS_ + lane] = v;
}

// ---------------------------------------------------------------------------
// Kernel 3: grouping. One block per (b, m). Gather 64 contiguous channels per
// index from the transposed features (256B coalesced per sample), plus the
// xyz diff; stage in a 67x33 smem tile; write output fully coalesced.
// ---------------------------------------------------------------------------
__global__ void group_kernel(const float* __restrict__ xyz,
                             const float* __restrict__ new_xyz,
                             float* __restrict__ out) {
    __shared__ int   sidx[NS_];
    __shared__ float tile[COUT_][33];

    const int bm = blockIdx.x;
    const int b  = bm >> 10;
    const int m  = bm & (M_ - 1);
    const int t  = threadIdx.x;          // 256 threads
    const int w  = t >> 5;
    const int lane = t & 31;

    if (t < NS_) sidx[t] = g_idx[(size_t)bm * NS_ + t];
    __syncthreads();

    const float* ftb = g_ft + (size_t)b * N_ * C_;
    const float* qp  = new_xyz + ((size_t)b * M_ + m) * 3;

#pragma unroll
    for (int k = 0; k < 4; k++) {
        const int s = w + k * 8;         // 8 warps cover 32 samples
        const int n = sidx[s];
        const float* col = ftb + (size_t)n * C_;
        tile[3 + lane][s]      = col[lane];
        tile[3 + 32 + lane][s] = col[lane + 32];
        if (lane < 3)
            tile[lane][s] = xyz[((size_t)b * N_ + n) * 3 + lane] - qp[lane];
    }
    __syncthreads();

    float* ob = out + ((size_t)b * COUT_ * M_ + m) * NS_;
    for (int e = t; e < COUT_ * NS_; e += 256) {
        const int c = e >> 5;
        const int s = e & 31;
        ob[(size_t)c * M_ * NS_ + s] = tile[c][s];
    }
}

// ---------------------------------------------------------------------------
extern "C" void kernel_launch(void* const* d_in, const int* in_sizes, int n_in,
                              void* d_out, int out_size) {
    const float* xyz = nullptr;
    const float* new_xyz = nullptr;
    const float* feats = nullptr;
    for (int i = 0; i < n_in; i++) {
        if (in_sizes[i] == B_ * N_ * 3)      xyz     = (const float*)d_in[i];
        else if (in_sizes[i] == B_ * M_ * 3) new_xyz = (const float*)d_in[i];
        else if (in_sizes[i] == B_ * C_ * N_) feats  = (const float*)d_in[i];
    }
    float* out = (float*)d_out;

    ballquery_kernel<<<(B_ * M_) / 8, 256>>>(xyz, new_xyz);

    dim3 tgrid(N_ / 32, C_ / 32, B_);
    transpose_kernel<<<tgrid, dim3(8, 32)>>>(feats);

    group_kernel<<<B_ * M_, 256>>>(xyz, new_xyz, out);
}

// round 7
// speedup vs baseline: 1.2102x; 1.2102x over previous
#include <cuda_runtime.h>
#include <cstdint>

#define B_ 8
#define N_ 16384
#define M_ 1024
#define C_ 64
#define NS_ 32
#define COUT_ 67
#define R2_ 0.04f

#define BQ_BLOCKS ((B_ * M_) / 8)                    // 1024
#define TR_BLOCKS ((N_ / 32) * (C_ / 32) * B_)       // 8192

// Scratch: transposed features (B, N, C) = 32 MB, and ball-query indices = 1 MB.
__device__ float g_ft[(size_t)B_ * N_ * C_];
__device__ int   g_idx[(size_t)B_ * M_ * NS_];

// ---------------------------------------------------------------------------
// Phase 1 (fused): blocks [0, BQ_BLOCKS) do ball query; the rest transpose
// features. Ballquery is latency-bound with ~0% memory use; transpose is pure
// bandwidth — running them concurrently hides the transpose entirely.
// ---------------------------------------------------------------------------

__device__ __forceinline__ void bq_load(const float* __restrict__ xb, int base,
                                        int lane, float px[4], float py[4],
                                        float pz[4]) {
#pragma unroll
    for (int g = 0; g < 4; g++) {
        const float* p = xb + (size_t)(base + g * 32 + lane) * 3;
        px[g] = p[0]; py[g] = p[1]; pz[g] = p[2];
    }
}

__global__ void __launch_bounds__(256) phase1_kernel(
    const float* __restrict__ xyz, const float* __restrict__ new_xyz,
    const float* __restrict__ f) {

    if (blockIdx.x < BQ_BLOCKS) {
        // ================= ball query: one warp per query ==================
        __shared__ int sidx[8][NS_];

        const int tid  = threadIdx.x;
        const int w    = tid >> 5;
        const int lane = tid & 31;
        const int q    = blockIdx.x * 8 + w;
        const int b    = q >> 10;

        const float* xb = xyz + (size_t)b * N_ * 3;
        const float* qp = new_xyz + (size_t)q * 3;
        const float qx = qp[0], qy = qp[1], qz = qp[2];
        const unsigned ltm = (1u << lane) - 1u;

        int total = 0;
        float axp[4], ayp[4], azp[4];   // buffer A
        float bxp[4], byp[4], bzp[4];   // buffer B

        bq_load(xb, 0, lane, axp, ayp, azp);

        for (int n0 = 0; n0 < N_; n0 += 256) {
            // ---- half 1: prefetch B(n0+128), process A(n0) ----
            bq_load(xb, n0 + 128, lane, bxp, byp, bzp);
            {
                unsigned msk[4];
#pragma unroll
                for (int g = 0; g < 4; g++) {
                    const float dx = axp[g] - qx;
                    const float dy = ayp[g] - qy;
                    const float dz = azp[g] - qz;
                    msk[g] = __ballot_sync(0xffffffffu,
                                           dx * dx + dy * dy + dz * dz < R2_);
                }
#pragma unroll
                for (int g = 0; g < 4; g++) {
                    if (msk[g]) {
                        const int pos = total + __popc(msk[g] & ltm);
                        if (((msk[g] >> lane) & 1u) && pos < NS_)
                            sidx[w][pos] = n0 + g * 32 + lane;
                        total += __popc(msk[g]);
                    }
                }
            }
            if (total >= NS_) break;

            // ---- half 2: prefetch A(n0+256), process B(n0+128) ----
            if (n0 + 256 < N_)
                bq_load(xb, n0 + 256, lane, axp, ayp, azp);
            {
                unsigned msk[4];
#pragma unroll
                for (int g = 0; g < 4; g++) {
                    const float dx = bxp[g] - qx;
                    const float dy = byp[g] - qy;
                    const float dz = bzp[g] - qz;
                    msk[g] = __ballot_sync(0xffffffffu,
                                           dx * dx + dy * dy + dz * dz < R2_);
                }
#pragma unroll
                for (int g = 0; g < 4; g++) {
                    if (msk[g]) {
                        const int pos = total + __popc(msk[g] & ltm);
                        if (((msk[g] >> lane) & 1u) && pos < NS_)
                            sidx[w][pos] = n0 + 128 + g * 32 + lane;
                        total += __popc(msk[g]);
                    }
                }
            }
            if (total >= NS_) break;
        }

        __syncwarp();
        int v;
        if (total == 0) {
            v = N_ - 1;  // reference: all-invalid -> clamped gather
        } else {
            const int first = sidx[w][0];
            v = (lane < min(total, NS_)) ? sidx[w][lane] : first;
        }
        g_idx[(size_t)q * NS_ + lane] = v;

    } else {
        // ============ transpose features (B,C,N)->(B,N,C), float4 ==========
        __shared__ float tile[32][33];

        const int t  = blockIdx.x - BQ_BLOCKS;
        const int bx = t & 511;           // N/32 = 512
        const int by = (t >> 9) & 1;      // C/32 = 2
        const int bz = t >> 10;           // B
        const int n0 = bx * 32;
        const int c0 = by * 32;
        const int tx = threadIdx.x & 7;
        const int ty = threadIdx.x >> 3;

        const float* src = f + (size_t)bz * C_ * N_;
        float*       dst = g_ft + (size_t)bz * N_ * C_;

        const float4 v = *(const float4*)(src + (size_t)(c0 + ty) * N_ + n0 + tx * 4);
        tile[ty][tx * 4 + 0] = v.x;
        tile[ty][tx * 4 + 1] = v.y;
        tile[ty][tx * 4 + 2] = v.z;
        tile[ty][tx * 4 + 3] = v.w;
        __syncthreads();

        float4 o;
        o.x = tile[tx * 4 + 0][ty];
        o.y = tile[tx * 4 + 1][ty];
        o.z = tile[tx * 4 + 2][ty];
        o.w = tile[tx * 4 + 3][ty];
        *(float4*)(dst + (size_t)(n0 + ty) * C_ + c0 + tx * 4) = o;
    }
}

// ---------------------------------------------------------------------------
// Kernel 2: grouping. One block per (b, m). Gather 64 contiguous channels per
// index from the transposed features (256B coalesced per sample), plus the
// xyz diff; stage in a 67x33 smem tile; write output fully coalesced.
// ---------------------------------------------------------------------------
__global__ void group_kernel(const float* __restrict__ xyz,
                             const float* __restrict__ new_xyz,
                             float* __restrict__ out) {
    __shared__ int   sidx[NS_];
    __shared__ float tile[COUT_][33];

    const int bm = blockIdx.x;
    const int b  = bm >> 10;
    const int m  = bm & (M_ - 1);
    const int t  = threadIdx.x;          // 256 threads
    const int w  = t >> 5;
    const int lane = t & 31;

    if (t < NS_) sidx[t] = g_idx[(size_t)bm * NS_ + t];
    __syncthreads();

    const float* ftb = g_ft + (size_t)b * N_ * C_;
    const float* qp  = new_xyz + ((size_t)b * M_ + m) * 3;

#pragma unroll
    for (int k = 0; k < 4; k++) {
        const int s = w + k * 8;         // 8 warps cover 32 samples
        const int n = sidx[s];
        const float* col = ftb + (size_t)n * C_;
        tile[3 + lane][s]      = col[lane];
        tile[3 + 32 + lane][s] = col[lane + 32];
        if (lane < 3)
            tile[lane][s] = xyz[((size_t)b * N_ + n) * 3 + lane] - qp[lane];
    }
    __syncthreads();

    float* ob = out + ((size_t)b * COUT_ * M_ + m) * NS_;
    for (int e = t; e < COUT_ * NS_; e += 256) {
        const int c = e >> 5;
        const int s = e & 31;
        ob[(size_t)c * M_ * NS_ + s] = tile[c][s];
    }
}

// ---------------------------------------------------------------------------
extern "C" void kernel_launch(void* const* d_in, const int* in_sizes, int n_in,
                              void* d_out, int out_size) {
    const float* xyz = nullptr;
    const float* new_xyz = nullptr;
    const float* feats = nullptr;
    for (int i = 0; i < n_in; i++) {
        if (in_sizes[i] == B_ * N_ * 3)      xyz     = (const float*)d_in[i];
        else if (in_sizes[i] == B_ * M_ * 3) new_xyz = (const float*)d_in[i];
        else if (in_sizes[i] == B_ * C_ * N_) feats  = (const float*)d_in[i];
    }
    float* out = (float*)d_out;

    phase1_kernel<<<BQ_BLOCKS + TR_BLOCKS, 256>>>(xyz, new_xyz, feats);
    group_kernel<<<B_ * M_, 256>>>(xyz, new_xyz, out);
}